// round 5
// baseline (speedup 1.0000x reference)
#include <cuda_runtime.h>
#include <math.h>

#define N_NODES 260000
#define N_EDGES 8320000
#define N_GRAPHS 10000
#define GN 26
#define SCAN_BLOCKS ((N_NODES + 1023) / 1024)   // 254

// ---- device-global scratch (no allocation allowed) ----
__device__ int    g_cnt[N_NODES];       // in-degree
__device__ int    g_off[N_NODES];       // CSR offsets (exclusive scan of cnt)
__device__ int    g_cur[N_NODES];       // write cursors for reorder
__device__ int    g_bsum[256];          // scan block sums
__device__ int    g_csr[N_EDGES];       // source node per incoming edge, grouped by dest
__device__ float4 g_sx[N_NODES];        // layer-1 neighbor sums of x
__device__ float4 g_z4[N_NODES * 4];    // z = h1@W2^T, 64B stride (12 floats used, [11]=0)
__device__ float4 g_g4[N_GRAPHS];       // per-graph pooled sums

__device__ __forceinline__ void red4(float* p, float a, float b, float c, float d) {
    asm volatile("red.global.add.v4.f32 [%0], {%1,%2,%3,%4};"
                 :: "l"(__cvta_generic_to_global(p)), "f"(a), "f"(b), "f"(c), "f"(d)
                 : "memory");
}

// ---------------- K0: zero small scratch ----------------
__global__ void zero_kernel() {
    int i = blockIdx.x * blockDim.x + threadIdx.x;
    if (i < N_NODES)  g_cnt[i] = 0;
    if (i < N_GRAPHS) g_g4[i] = make_float4(0.f, 0.f, 0.f, 0.f);
}

// ---------------- K1: degree histogram ----------------
__global__ void hist_kernel(const int* __restrict__ ei) {
    int e = blockIdx.x * blockDim.x + threadIdx.x;
    if (e >= N_EDGES) return;
    int c = __ldg(&ei[N_EDGES + e]);
    atomicAdd(&g_cnt[c], 1);            // no return -> RED
}

// ---------------- K2a/b/c: exclusive scan of g_cnt -> g_off, g_cur ----------------
__global__ void scan1_kernel() {
    __shared__ int sh[1024];
    int t = threadIdx.x;
    int gid = blockIdx.x * 1024 + t;
    int v = (gid < N_NODES) ? g_cnt[gid] : 0;
    sh[t] = v;
    __syncthreads();
#pragma unroll
    for (int o = 1; o < 1024; o <<= 1) {
        int add = (t >= o) ? sh[t - o] : 0;
        __syncthreads();
        sh[t] += add;
        __syncthreads();
    }
    if (gid < N_NODES) g_off[gid] = sh[t] - v;       // exclusive
    if (t == 1023) g_bsum[blockIdx.x] = sh[1023];    // block total
}

__global__ void scan2_kernel() {
    __shared__ int sh[256];
    int t = threadIdx.x;
    int v = (t < SCAN_BLOCKS) ? g_bsum[t] : 0;
    sh[t] = v;
    __syncthreads();
#pragma unroll
    for (int o = 1; o < 256; o <<= 1) {
        int add = (t >= o) ? sh[t - o] : 0;
        __syncthreads();
        sh[t] += add;
        __syncthreads();
    }
    if (t < SCAN_BLOCKS) g_bsum[t] = sh[t] - v;      // exclusive block bases
}

__global__ void scan3_kernel() {
    int gid = blockIdx.x * blockDim.x + threadIdx.x;
    if (gid >= N_NODES) return;
    int o = g_off[gid] + g_bsum[gid >> 10];
    g_off[gid] = o;
    g_cur[gid] = o;
}

// ---------------- K3: CSR reorder ----------------
__global__ void reorder_kernel(const int* __restrict__ ei) {
    int e = blockIdx.x * blockDim.x + threadIdx.x;
    if (e >= N_EDGES) return;
    int r = __ldg(&ei[e]);
    int c = __ldg(&ei[N_EDGES + e]);
    int p = atomicAdd(&g_cur[c], 1);
    g_csr[p] = r;
}

// ---------------- K4: gather pass 1 — sum x over in-neighbors (warp per node) ----------------
__global__ void gather1_kernel(const float4* __restrict__ x) {
    int gt = blockIdx.x * blockDim.x + threadIdx.x;
    int w = gt >> 5;
    int lane = gt & 31;
    if (w >= N_NODES) return;
    int base = g_off[w];
    int d = g_cnt[w];
    float sx = 0.f, sy = 0.f, sz = 0.f, sw = 0.f;
    for (int j = lane; j < d; j += 32) {
        int r = __ldg(&g_csr[base + j]);
        float4 v = __ldg(&x[r]);
        sx += v.x; sy += v.y; sz += v.z; sw += v.w;
    }
#pragma unroll
    for (int o = 16; o > 0; o >>= 1) {
        sx += __shfl_xor_sync(0xFFFFFFFFu, sx, o);
        sy += __shfl_xor_sync(0xFFFFFFFFu, sy, o);
        sz += __shfl_xor_sync(0xFFFFFFFFu, sz, o);
        sw += __shfl_xor_sync(0xFFFFFFFFu, sw, o);
    }
    if (lane == 0) g_sx[w] = make_float4(sx, sy, sz, sw);
}

// ---------------- K5: node pass 1 — h1 = tanh(...), z = h1 @ W2^T ----------------
__global__ void node1_kernel(const float4* __restrict__ x,
                             const float* __restrict__ W1,
                             const float* __restrict__ b1,
                             const float* __restrict__ W2) {
    __shared__ float sW1[26 * 4];
    __shared__ float sb1[26];
    __shared__ float sW2[11 * 26];
    int t = threadIdx.x;
    for (int i = t; i < 26 * 4; i += blockDim.x)  sW1[i] = W1[i];
    for (int i = t; i < 26; i += blockDim.x)      sb1[i] = b1[i];
    for (int i = t; i < 11 * 26; i += blockDim.x) sW2[i] = W2[i];
    __syncthreads();

    int i = blockIdx.x * blockDim.x + t;
    if (i >= N_NODES) return;

    float4 s  = g_sx[i];
    float4 xi = __ldg(&x[i]);
    float t0 = s.x + xi.x, t1 = s.y + xi.y, t2 = s.z + xi.z, t3 = s.w + xi.w;
    float c1 = (float)g_cnt[i] + 1.0f;

    float h[26];
#pragma unroll
    for (int j = 0; j < 26; j++) {
        float a = fmaf(sW1[j * 4 + 0], t0,
                  fmaf(sW1[j * 4 + 1], t1,
                  fmaf(sW1[j * 4 + 2], t2,
                  fmaf(sW1[j * 4 + 3], t3, c1 * sb1[j]))));
        h[j] = tanhf(a);
    }

    float z[12];
#pragma unroll
    for (int k = 0; k < 11; k++) {
        float a = 0.f;
#pragma unroll
        for (int j = 0; j < 26; j++) a = fmaf(sW2[k * 26 + j], h[j], a);
        z[k] = a;
    }
    z[11] = 0.f;

    float4* zp = &g_z4[i * 4];
    zp[0] = make_float4(z[0], z[1], z[2],  z[3]);
    zp[1] = make_float4(z[4], z[5], z[6],  z[7]);
    zp[2] = make_float4(z[8], z[9], z[10], z[11]);
    // zp[3] never read
}

// ---------------- K6: gather pass 2 fused with tanh/maxpool/graph-sum (warp per node) ----------------
__global__ void gather2_kernel(const float* __restrict__ b2) {
    int gt = blockIdx.x * blockDim.x + threadIdx.x;
    int w = gt >> 5;
    int lane = gt & 31;
    if (w >= N_NODES) return;
    int base = g_off[w];
    int d = g_cnt[w];

    float a0, a1, a2, a3, a4, a5, a6, a7, a8, a9, a10, a11;
    if (lane == 0) {
        // seed with self-loop contribution z[w]
        const float4* zp = &g_z4[(size_t)w * 4];
        float4 p = zp[0], q = zp[1], r2 = zp[2];
        a0 = p.x;  a1 = p.y;  a2 = p.z;  a3 = p.w;
        a4 = q.x;  a5 = q.y;  a6 = q.z;  a7 = q.w;
        a8 = r2.x; a9 = r2.y; a10 = r2.z; a11 = r2.w;
    } else {
        a0=a1=a2=a3=a4=a5=a6=a7=a8=a9=a10=a11=0.f;
    }

    for (int j = lane; j < d; j += 32) {
        int r = __ldg(&g_csr[base + j]);
        const float4* zp = &g_z4[(size_t)r * 4];
        float4 p = __ldg(&zp[0]);
        float4 q = __ldg(&zp[1]);
        float4 s = __ldg(&zp[2]);
        a0 += p.x;  a1 += p.y;  a2 += p.z;  a3 += p.w;
        a4 += q.x;  a5 += q.y;  a6 += q.z;  a7 += q.w;
        a8 += s.x;  a9 += s.y;  a10 += s.z; a11 += s.w;
    }

#pragma unroll
    for (int o = 16; o > 0; o >>= 1) {
        a0  += __shfl_xor_sync(0xFFFFFFFFu, a0,  o);
        a1  += __shfl_xor_sync(0xFFFFFFFFu, a1,  o);
        a2  += __shfl_xor_sync(0xFFFFFFFFu, a2,  o);
        a3  += __shfl_xor_sync(0xFFFFFFFFu, a3,  o);
        a4  += __shfl_xor_sync(0xFFFFFFFFu, a4,  o);
        a5  += __shfl_xor_sync(0xFFFFFFFFu, a5,  o);
        a6  += __shfl_xor_sync(0xFFFFFFFFu, a6,  o);
        a7  += __shfl_xor_sync(0xFFFFFFFFu, a7,  o);
        a8  += __shfl_xor_sync(0xFFFFFFFFu, a8,  o);
        a9  += __shfl_xor_sync(0xFFFFFFFFu, a9,  o);
        a10 += __shfl_xor_sync(0xFFFFFFFFu, a10, o);
        a11 += __shfl_xor_sync(0xFFFFFFFFu, a11, o);
    }

    if (lane == 0) {
        float c1 = (float)d + 1.0f;
        float v0  = tanhf(a0  + c1 * __ldg(&b2[0]));
        float v1  = tanhf(a1  + c1 * __ldg(&b2[1]));
        float v2  = tanhf(a2  + c1 * __ldg(&b2[2]));
        float v3  = tanhf(a3  + c1 * __ldg(&b2[3]));
        float v4  = tanhf(a4  + c1 * __ldg(&b2[4]));
        float v5  = tanhf(a5  + c1 * __ldg(&b2[5]));
        float v6  = tanhf(a6  + c1 * __ldg(&b2[6]));
        float v7  = tanhf(a7  + c1 * __ldg(&b2[7]));
        float v8  = tanhf(a8  + c1 * __ldg(&b2[8]));
        float v9  = tanhf(a9  + c1 * __ldg(&b2[9]));
        float v10 = tanhf(a10 + c1 * __ldg(&b2[10]));
        // MaxPool1d(3, stride 3, left-pad 1): (-inf,v0,v1),(v2,v3,v4),(v5,v6,v7),(v8,v9,v10)
        float p0 = fmaxf(v0, v1);
        float p1 = fmaxf(fmaxf(v2, v3), v4);
        float p2 = fmaxf(fmaxf(v5, v6), v7);
        float p3 = fmaxf(fmaxf(v8, v9), v10);
        red4((float*)&g_g4[w / GN], p0, p1, p2, p3);
    }
}

// ---------------- K7: per-graph linear + softmax ----------------
__global__ void final_kernel(const float* __restrict__ Wl,
                             const float* __restrict__ bl,
                             float* __restrict__ out) {
    int g = blockIdx.x * blockDim.x + threadIdx.x;
    if (g >= N_GRAPHS) return;
    float4 gv = g_g4[g];
    float o0 = fmaf(Wl[0], gv.x, fmaf(Wl[1], gv.y, fmaf(Wl[2], gv.z, fmaf(Wl[3], gv.w, bl[0]))));
    float o1 = fmaf(Wl[4], gv.x, fmaf(Wl[5], gv.y, fmaf(Wl[6], gv.z, fmaf(Wl[7], gv.w, bl[1]))));
    float m = fmaxf(o0, o1);
    float e0 = expf(o0 - m), e1 = expf(o1 - m);
    float inv = 1.0f / (e0 + e1);
    out[g * 2 + 0] = e0 * inv;
    out[g * 2 + 1] = e1 * inv;
}

extern "C" void kernel_launch(void* const* d_in, const int* in_sizes, int n_in,
                              void* d_out, int out_size) {
    const float4* x  = (const float4*)d_in[0];   // [260000,4] f32
    const int*    ei = (const int*)d_in[1];      // [2, 8320000] i32
    const float*  W1 = (const float*)d_in[2];    // [26,4]
    const float*  b1 = (const float*)d_in[3];    // [26]
    const float*  W2 = (const float*)d_in[4];    // [11,26]
    const float*  b2 = (const float*)d_in[5];    // [11]
    const float*  Wl = (const float*)d_in[6];    // [2,4]
    const float*  bl = (const float*)d_in[7];    // [2]
    float* out = (float*)d_out;                  // [10000,2]

    const int T = 256;
    const int EB = (N_EDGES + T - 1) / T;
    const int NB = (N_NODES + T - 1) / T;
    const int WB = (N_NODES * 32 + T - 1) / T;   // warp-per-node grids

    zero_kernel<<<NB, T>>>();
    hist_kernel<<<EB, T>>>(ei);
    scan1_kernel<<<SCAN_BLOCKS, 1024>>>();
    scan2_kernel<<<1, 256>>>();
    scan3_kernel<<<NB, T>>>();
    reorder_kernel<<<EB, T>>>(ei);
    gather1_kernel<<<WB, T>>>(x);
    node1_kernel<<<NB, T>>>(x, W1, b1, W2);
    gather2_kernel<<<WB, T>>>(b2);
    final_kernel<<<(N_GRAPHS + T - 1) / T, T>>>(Wl, bl, out);
}

// round 6
// speedup vs baseline: 1.4934x; 1.4934x over previous
#include <cuda_runtime.h>
#include <cuda_fp16.h>
#include <math.h>

#define N_NODES 260000
#define N_EDGES 8320000
#define N_GRAPHS 10000
#define GN 26

// ---- device-global scratch (no allocation allowed) ----
// xs: per-node [sum_x(4) | cnt(1), pad(3)]  (two float4, self x pre-seeded)
__device__ float4 g_xs4[N_NODES * 2];     // 8.3 MB
// zh: per-node z in f16, 12 halves used + 4 pad, 32B stride (one sector)
__device__ uint4  g_zh[N_NODES * 2];      // 8.3 MB
// agg2: f32 scatter target, 48B stride, pre-seeded with self z in node1
__device__ float4 g_agg4[N_NODES * 3];    // 12.5 MB
// per-graph pooled sums
__device__ float4 g_g4[N_GRAPHS];         // 160 KB

__device__ __forceinline__ void red4(float* p, float a, float b, float c, float d) {
    asm volatile("red.global.add.v4.f32 [%0], {%1,%2,%3,%4};"
                 :: "l"(__cvta_generic_to_global(p)), "f"(a), "f"(b), "f"(c), "f"(d)
                 : "memory");
}
__device__ __forceinline__ void red1(float* p, float a) {
    asm volatile("red.global.add.f32 [%0], %1;"
                 :: "l"(__cvta_generic_to_global(p)), "f"(a)
                 : "memory");
}
__device__ __forceinline__ unsigned packh2(float a, float b) {
    __half2 h = __floats2half2_rn(a, b);
    return *reinterpret_cast<unsigned*>(&h);
}
__device__ __forceinline__ float2 unpackh2(unsigned u) {
    __half2 h = *reinterpret_cast<__half2*>(&u);
    return __half22float2(h);
}

// ---------------- K0: init — seed xs with self x, zero counters & graph sums ----------------
__global__ void init_kernel(const float4* __restrict__ x) {
    int i = blockIdx.x * blockDim.x + threadIdx.x;
    if (i < N_NODES) {
        g_xs4[i * 2]     = __ldg(&x[i]);                     // self-loop x
        g_xs4[i * 2 + 1] = make_float4(0.f, 0.f, 0.f, 0.f);  // cnt = 0
    }
    if (i < N_GRAPHS) g_g4[i] = make_float4(0.f, 0.f, 0.f, 0.f);
}

// ---------------- K1: edge pass 1 — scatter raw x + degree ----------------
__global__ void edge1_kernel(const int* __restrict__ ei, const float4* __restrict__ x) {
    int e = blockIdx.x * blockDim.x + threadIdx.x;
    if (e >= N_EDGES) return;
    int r = __ldg(&ei[e]);
    int c = __ldg(&ei[N_EDGES + e]);
    float4 v = __ldg(&x[r]);
    float* p = (float*)&g_xs4[c * 2];
    red4(p, v.x, v.y, v.z, v.w);
    red1(p + 4, 1.0f);
}

// ---------------- K2: node pass 1 — h1 = tanh(...), z = h1 @ W2^T (f16) + seed agg ----------------
__global__ void node1_kernel(const float* __restrict__ W1,
                             const float* __restrict__ b1,
                             const float* __restrict__ W2) {
    __shared__ float sW1[26 * 4];
    __shared__ float sb1[26];
    __shared__ float sW2[11 * 26];
    int t = threadIdx.x;
    for (int i = t; i < 26 * 4; i += blockDim.x)  sW1[i] = W1[i];
    for (int i = t; i < 26; i += blockDim.x)      sb1[i] = b1[i];
    for (int i = t; i < 11 * 26; i += blockDim.x) sW2[i] = W2[i];
    __syncthreads();

    int i = blockIdx.x * blockDim.x + t;
    if (i >= N_NODES) return;

    float4 s = g_xs4[i * 2];                       // includes self x
    float c1 = ((const float*)&g_xs4[i * 2])[4] + 1.0f;

    float h[26];
#pragma unroll
    for (int j = 0; j < 26; j++) {
        float a = fmaf(sW1[j * 4 + 0], s.x,
                  fmaf(sW1[j * 4 + 1], s.y,
                  fmaf(sW1[j * 4 + 2], s.z,
                  fmaf(sW1[j * 4 + 3], s.w, c1 * sb1[j]))));
        h[j] = tanhf(a);
    }

    float z[12];
#pragma unroll
    for (int k = 0; k < 11; k++) {
        float a = 0.f;
#pragma unroll
        for (int j = 0; j < 26; j++) a = fmaf(sW2[k * 26 + j], h[j], a);
        z[k] = a;
    }
    z[11] = 0.f;

    // f16 record for the edge-pass gather (one 32B sector)
    uint4 A, B;
    A.x = packh2(z[0], z[1]);  A.y = packh2(z[2],  z[3]);
    A.z = packh2(z[4], z[5]);  A.w = packh2(z[6],  z[7]);
    B.x = packh2(z[8], z[9]);  B.y = packh2(z[10], z[11]);
    B.z = 0u; B.w = 0u;
    g_zh[i * 2]     = A;
    g_zh[i * 2 + 1] = B;

    // seed agg with the (exact f32) self-loop contribution — replaces zeroing
    float4* ap = &g_agg4[i * 3];
    ap[0] = make_float4(z[0], z[1], z[2],  z[3]);
    ap[1] = make_float4(z[4], z[5], z[6],  z[7]);
    ap[2] = make_float4(z[8], z[9], z[10], z[11]);
}

// ---------------- K3: edge pass 2 — gather f16 z (1 sector) + 3x red.v4.f32 ----------------
__global__ void edge2_kernel(const int* __restrict__ ei) {
    int e = blockIdx.x * blockDim.x + threadIdx.x;
    if (e >= N_EDGES) return;
    int r = __ldg(&ei[e]);
    int c = __ldg(&ei[N_EDGES + e]);

    const uint4* zp = &g_zh[r * 2];
    uint4 A = __ldg(zp);
    uint2 B = __ldg((const uint2*)(zp + 1));   // same 32B sector as A's tail

    float2 f0 = unpackh2(A.x), f1 = unpackh2(A.y);
    float2 f2 = unpackh2(A.z), f3 = unpackh2(A.w);
    float2 f4 = unpackh2(B.x), f5 = unpackh2(B.y);

    float* p = (float*)&g_agg4[c * 3];
    red4(p,     f0.x, f0.y, f1.x, f1.y);
    red4(p + 4, f2.x, f2.y, f3.x, f3.y);
    red4(p + 8, f4.x, f4.y, f5.x, f5.y);
}

// ---------------- K4: node pass 2 — tanh, maxpool, graph-sum scatter ----------------
__global__ void node2_kernel(const float* __restrict__ b2) {
    __shared__ float sb2[11];
    int t = threadIdx.x;
    if (t < 11) sb2[t] = b2[t];
    __syncthreads();

    int i = blockIdx.x * blockDim.x + t;
    if (i >= N_NODES) return;

    float c1 = ((const float*)&g_xs4[i * 2])[4] + 1.0f;
    const float4* ap = &g_agg4[i * 3];
    float4 a0 = ap[0], a1 = ap[1], a2 = ap[2];
    float av[12] = {a0.x, a0.y, a0.z, a0.w, a1.x, a1.y, a1.z, a1.w, a2.x, a2.y, a2.z, a2.w};
    float v[11];
#pragma unroll
    for (int k = 0; k < 11; k++)
        v[k] = tanhf(av[k] + c1 * sb2[k]);

    // MaxPool1d(3, stride 3, left-pad 1): (-inf,v0,v1),(v2,v3,v4),(v5,v6,v7),(v8,v9,v10)
    float p0 = fmaxf(v[0], v[1]);
    float p1 = fmaxf(fmaxf(v[2], v[3]), v[4]);
    float p2 = fmaxf(fmaxf(v[5], v[6]), v[7]);
    float p3 = fmaxf(fmaxf(v[8], v[9]), v[10]);

    red4((float*)&g_g4[i / GN], p0, p1, p2, p3);
}

// ---------------- K5: per-graph linear + softmax ----------------
__global__ void final_kernel(const float* __restrict__ Wl,
                             const float* __restrict__ bl,
                             float* __restrict__ out) {
    int g = blockIdx.x * blockDim.x + threadIdx.x;
    if (g >= N_GRAPHS) return;
    float4 gv = g_g4[g];
    float o0 = fmaf(Wl[0], gv.x, fmaf(Wl[1], gv.y, fmaf(Wl[2], gv.z, fmaf(Wl[3], gv.w, bl[0]))));
    float o1 = fmaf(Wl[4], gv.x, fmaf(Wl[5], gv.y, fmaf(Wl[6], gv.z, fmaf(Wl[7], gv.w, bl[1]))));
    float m = fmaxf(o0, o1);
    float e0 = expf(o0 - m), e1 = expf(o1 - m);
    float inv = 1.0f / (e0 + e1);
    out[g * 2 + 0] = e0 * inv;
    out[g * 2 + 1] = e1 * inv;
}

extern "C" void kernel_launch(void* const* d_in, const int* in_sizes, int n_in,
                              void* d_out, int out_size) {
    const float4* x  = (const float4*)d_in[0];   // [260000,4] f32
    const int*    ei = (const int*)d_in[1];      // [2, 8320000] i32
    const float*  W1 = (const float*)d_in[2];    // [26,4]
    const float*  b1 = (const float*)d_in[3];    // [26]
    const float*  W2 = (const float*)d_in[4];    // [11,26]
    const float*  b2 = (const float*)d_in[5];    // [11]
    const float*  Wl = (const float*)d_in[6];    // [2,4]
    const float*  bl = (const float*)d_in[7];    // [2]
    float* out = (float*)d_out;                  // [10000,2]

    const int T = 256;
    const int EB = (N_EDGES + T - 1) / T;
    const int NB = (N_NODES + T - 1) / T;

    init_kernel<<<NB, T>>>(x);
    edge1_kernel<<<EB, T>>>(ei, x);
    node1_kernel<<<NB, T>>>(W1, b1, W2);
    edge2_kernel<<<EB, T>>>(ei);
    node2_kernel<<<NB, T>>>(b2);
    final_kernel<<<(N_GRAPHS + T - 1) / T, T>>>(Wl, bl, out);
}

// round 7
// speedup vs baseline: 1.9856x; 1.3296x over previous
#include <cuda_runtime.h>
#include <cuda_fp16.h>
#include <math.h>

#define N_NODES 260000
#define N_EDGES 8320000
#define N_GRAPHS 10000
#define GN 26

// ---- device-global scratch ----
__device__ uint2  g_xh[N_NODES];        // x quantized to f16 (4 halves, 8B)
__device__ uint4  g_xs[N_NODES];        // accum: [sumx f16 x4 | deg f16 | 3 pad halves]
__device__ uint4  g_zh[N_NODES * 2];    // z in f16: 12 halves used, 32B stride
// agg: 32B/node: [ch0-7 f16 (16B) | ch8,9,10 f32 + pad (16B)]
__device__ uint4  g_agg[N_NODES * 2];
__device__ float4 g_g4[N_GRAPHS];       // per-graph pooled sums

__device__ __forceinline__ void red4f(float* p, float a, float b, float c, float d) {
    asm volatile("red.global.add.v4.f32 [%0], {%1,%2,%3,%4};"
                 :: "l"(__cvta_generic_to_global(p)), "f"(a), "f"(b), "f"(c), "f"(d)
                 : "memory");
}
__device__ __forceinline__ void redh8(void* p, unsigned a, unsigned b, unsigned c, unsigned d) {
    asm volatile("red.global.add.noftz.v4.f16x2 [%0], {%1,%2,%3,%4};"
                 :: "l"(__cvta_generic_to_global(p)), "r"(a), "r"(b), "r"(c), "r"(d)
                 : "memory");
}
__device__ __forceinline__ unsigned packh2(float a, float b) {
    __half2 h = __floats2half2_rn(a, b);
    return *reinterpret_cast<unsigned*>(&h);
}
__device__ __forceinline__ float2 unpackh2(unsigned u) {
    __half2 h = *reinterpret_cast<__half2*>(&u);
    return __half22float2(h);
}

// ---------------- K0: init — quantize x to f16, zero accumulators ----------------
__global__ void init_kernel(const float4* __restrict__ x) {
    int i = blockIdx.x * blockDim.x + threadIdx.x;
    if (i < N_NODES) {
        float4 v = __ldg(&x[i]);
        g_xh[i] = make_uint2(packh2(v.x, v.y), packh2(v.z, v.w));
        g_xs[i] = make_uint4(0u, 0u, 0u, 0u);
    }
    if (i < N_GRAPHS) g_g4[i] = make_float4(0.f, 0.f, 0.f, 0.f);
}

// ---------------- K1: edge pass 1 — ONE red.v4.f16x2: [sum x (f16), deg] ----------------
__global__ void edge1_kernel(const int* __restrict__ ei) {
    int e = blockIdx.x * blockDim.x + threadIdx.x;
    if (e >= N_EDGES) return;
    int r = __ldg(&ei[e]);
    int c = __ldg(&ei[N_EDGES + e]);
    uint2 v = __ldg(&g_xh[r]);
    // halves: [x0,x1, x2,x3, 1.0,0, 0,0]  -> deg counts exactly in f16
    redh8(&g_xs[c], v.x, v.y, 0x00003C00u, 0u);
}

// ---------------- K2: node pass 1 — h1 = tanh(...), z = h1@W2^T; seed agg ----------------
__global__ void node1_kernel(const float4* __restrict__ x,
                             const float* __restrict__ W1,
                             const float* __restrict__ b1,
                             const float* __restrict__ W2) {
    __shared__ float sW1[26 * 4];
    __shared__ float sb1[26];
    __shared__ float sW2[11 * 26];
    int t = threadIdx.x;
    for (int i = t; i < 26 * 4; i += blockDim.x)  sW1[i] = W1[i];
    for (int i = t; i < 26; i += blockDim.x)      sb1[i] = b1[i];
    for (int i = t; i < 11 * 26; i += blockDim.x) sW2[i] = W2[i];
    __syncthreads();

    int i = blockIdx.x * blockDim.x + t;
    if (i >= N_NODES) return;

    uint4 sv = g_xs[i];
    float2 s01 = unpackh2(sv.x), s23 = unpackh2(sv.y);
    float  deg = unpackh2(sv.z).x;
    float4 xi = __ldg(&x[i]);                 // self-loop: exact f32
    float t0 = s01.x + xi.x, t1 = s01.y + xi.y;
    float t2 = s23.x + xi.z, t3 = s23.y + xi.w;
    float c1 = deg + 1.0f;

    float h[26];
#pragma unroll
    for (int j = 0; j < 26; j++) {
        float a = fmaf(sW1[j * 4 + 0], t0,
                  fmaf(sW1[j * 4 + 1], t1,
                  fmaf(sW1[j * 4 + 2], t2,
                  fmaf(sW1[j * 4 + 3], t3, c1 * sb1[j]))));
        h[j] = tanhf(a);
    }

    float z[12];
#pragma unroll
    for (int k = 0; k < 11; k++) {
        float a = 0.f;
#pragma unroll
        for (int j = 0; j < 26; j++) a = fmaf(sW2[k * 26 + j], h[j], a);
        z[k] = a;
    }
    z[11] = 0.f;

    // f16 record for the edge-2 gather (ch0..7 feed the f16 red raw)
    uint4 A;
    A.x = packh2(z[0], z[1]);  A.y = packh2(z[2], z[3]);
    A.z = packh2(z[4], z[5]);  A.w = packh2(z[6], z[7]);
    uint4 B;
    B.x = packh2(z[8], z[9]);  B.y = packh2(z[10], 0.f);
    B.z = 0u; B.w = 0u;
    g_zh[i * 2]     = A;
    g_zh[i * 2 + 1] = B;

    // seed agg with self-loop z: ch0-7 f16, ch8-10 exact f32
    g_agg[i * 2] = A;
    float4 F = make_float4(z[8], z[9], z[10], 0.f);
    *reinterpret_cast<float4*>(&g_agg[i * 2 + 1]) = F;
}

// ---------------- K3: edge pass 2 — TWO reds: 8 ch f16 + 3 ch f32 ----------------
__global__ void edge2_kernel(const int* __restrict__ ei) {
    int e = blockIdx.x * blockDim.x + threadIdx.x;
    if (e >= N_EDGES) return;
    int r = __ldg(&ei[e]);
    int c = __ldg(&ei[N_EDGES + e]);

    const uint4* zp = &g_zh[r * 2];
    uint4 A = __ldg(zp);                            // ch0..7, raw f16 words
    uint2 B = __ldg((const uint2*)(zp + 1));        // ch8..10 (+pad), same 32B sector

    redh8(&g_agg[c * 2], A.x, A.y, A.z, A.w);

    float2 f4 = unpackh2(B.x), f5 = unpackh2(B.y);
    red4f((float*)&g_agg[c * 2 + 1], f4.x, f4.y, f5.x, 0.f);
}

// ---------------- K4: node pass 2 — tanh, maxpool, graph-sum scatter ----------------
__global__ void node2_kernel(const float* __restrict__ b2) {
    __shared__ float sb2[11];
    int t = threadIdx.x;
    if (t < 11) sb2[t] = b2[t];
    __syncthreads();

    int i = blockIdx.x * blockDim.x + t;
    if (i >= N_NODES) return;

    float deg = unpackh2(g_xs[i].z).x;
    float c1 = deg + 1.0f;

    uint4  A = g_agg[i * 2];
    float4 F = *reinterpret_cast<const float4*>(&g_agg[i * 2 + 1]);
    float2 a01 = unpackh2(A.x), a23 = unpackh2(A.y);
    float2 a45 = unpackh2(A.z), a67 = unpackh2(A.w);

    float av[11] = {a01.x, a01.y, a23.x, a23.y, a45.x, a45.y, a67.x, a67.y,
                    F.x, F.y, F.z};
    float v[11];
#pragma unroll
    for (int k = 0; k < 11; k++)
        v[k] = tanhf(av[k] + c1 * sb2[k]);

    // MaxPool1d(3, stride 3, left-pad 1): (-inf,v0,v1),(v2,v3,v4),(v5,v6,v7),(v8,v9,v10)
    float p0 = fmaxf(v[0], v[1]);
    float p1 = fmaxf(fmaxf(v[2], v[3]), v[4]);
    float p2 = fmaxf(fmaxf(v[5], v[6]), v[7]);
    float p3 = fmaxf(fmaxf(v[8], v[9]), v[10]);

    red4f((float*)&g_g4[i / GN], p0, p1, p2, p3);
}

// ---------------- K5: per-graph linear + softmax ----------------
__global__ void final_kernel(const float* __restrict__ Wl,
                             const float* __restrict__ bl,
                             float* __restrict__ out) {
    int g = blockIdx.x * blockDim.x + threadIdx.x;
    if (g >= N_GRAPHS) return;
    float4 gv = g_g4[g];
    float o0 = fmaf(Wl[0], gv.x, fmaf(Wl[1], gv.y, fmaf(Wl[2], gv.z, fmaf(Wl[3], gv.w, bl[0]))));
    float o1 = fmaf(Wl[4], gv.x, fmaf(Wl[5], gv.y, fmaf(Wl[6], gv.z, fmaf(Wl[7], gv.w, bl[1]))));
    float m = fmaxf(o0, o1);
    float e0 = expf(o0 - m), e1 = expf(o1 - m);
    float inv = 1.0f / (e0 + e1);
    out[g * 2 + 0] = e0 * inv;
    out[g * 2 + 1] = e1 * inv;
}

extern "C" void kernel_launch(void* const* d_in, const int* in_sizes, int n_in,
                              void* d_out, int out_size) {
    const float4* x  = (const float4*)d_in[0];   // [260000,4] f32
    const int*    ei = (const int*)d_in[1];      // [2, 8320000] i32
    const float*  W1 = (const float*)d_in[2];    // [26,4]
    const float*  b1 = (const float*)d_in[3];    // [26]
    const float*  W2 = (const float*)d_in[4];    // [11,26]
    const float*  b2 = (const float*)d_in[5];    // [11]
    const float*  Wl = (const float*)d_in[6];    // [2,4]
    const float*  bl = (const float*)d_in[7];    // [2]
    float* out = (float*)d_out;                  // [10000,2]

    const int T = 256;
    const int EB = (N_EDGES + T - 1) / T;
    const int NB = (N_NODES + T - 1) / T;

    init_kernel<<<NB, T>>>(x);
    edge1_kernel<<<EB, T>>>(ei);
    node1_kernel<<<NB, T>>>(x, W1, b1, W2);
    edge2_kernel<<<EB, T>>>(ei);
    node2_kernel<<<NB, T>>>(b2);
    final_kernel<<<(N_GRAPHS + T - 1) / T, T>>>(Wl, bl, out);
}

// round 8
// speedup vs baseline: 2.0276x; 1.0212x over previous
#include <cuda_runtime.h>
#include <cuda_fp16.h>
#include <math.h>

#define N_NODES 260000
#define N_EDGES 8320000
#define N_GRAPHS 10000
#define GN 26

// ---- device-global scratch ----
__device__ uint2  g_xh[N_NODES];        // x quantized to f16 (4 halves, 8B)
__device__ uint4  g_xs[N_NODES];        // accum: [sumx f16 x4 | deg f16 | 3 pad halves]
__device__ uint4  g_zh[N_NODES * 2];    // z in f16: 12 halves used, 32B stride
__device__ uint4  g_aggA[N_NODES];      // agg ch0-7, f16 accumulation (16B)
__device__ uint2  g_aggB[N_NODES];      // agg ch8-10 (+pad), f16 accumulation (8B), separate L2 lines
__device__ float4 g_g4[N_GRAPHS];       // per-graph pooled sums

__device__ __forceinline__ void red4f(float* p, float a, float b, float c, float d) {
    asm volatile("red.global.add.v4.f32 [%0], {%1,%2,%3,%4};"
                 :: "l"(__cvta_generic_to_global(p)), "f"(a), "f"(b), "f"(c), "f"(d)
                 : "memory");
}
__device__ __forceinline__ void redh8(void* p, unsigned a, unsigned b, unsigned c, unsigned d) {
    asm volatile("red.global.add.noftz.v4.f16x2 [%0], {%1,%2,%3,%4};"
                 :: "l"(__cvta_generic_to_global(p)), "r"(a), "r"(b), "r"(c), "r"(d)
                 : "memory");
}
__device__ __forceinline__ void redh4(void* p, unsigned a, unsigned b) {
    asm volatile("red.global.add.noftz.v2.f16x2 [%0], {%1,%2};"
                 :: "l"(__cvta_generic_to_global(p)), "r"(a), "r"(b)
                 : "memory");
}
__device__ __forceinline__ unsigned packh2(float a, float b) {
    __half2 h = __floats2half2_rn(a, b);
    return *reinterpret_cast<unsigned*>(&h);
}
__device__ __forceinline__ float2 unpackh2(unsigned u) {
    __half2 h = *reinterpret_cast<__half2*>(&u);
    return __half22float2(h);
}

// ---------------- K0: init — quantize x to f16, zero accumulators ----------------
__global__ void init_kernel(const float4* __restrict__ x) {
    int i = blockIdx.x * blockDim.x + threadIdx.x;
    if (i < N_NODES) {
        float4 v = __ldg(&x[i]);
        g_xh[i] = make_uint2(packh2(v.x, v.y), packh2(v.z, v.w));
        g_xs[i] = make_uint4(0u, 0u, 0u, 0u);
    }
    if (i < N_GRAPHS) g_g4[i] = make_float4(0.f, 0.f, 0.f, 0.f);
}

// ---------------- K1: edge pass 1 — ONE red.v4.f16x2: [sum x (f16), deg] ----------------
__global__ void edge1_kernel(const int* __restrict__ ei) {
    int e = blockIdx.x * blockDim.x + threadIdx.x;
    if (e >= N_EDGES) return;
    int r = __ldg(&ei[e]);
    int c = __ldg(&ei[N_EDGES + e]);
    uint2 v = __ldg(&g_xh[r]);
    // halves: [x0,x1, x2,x3, 1.0,0, 0,0]  -> deg counts exactly in f16
    redh8(&g_xs[c], v.x, v.y, 0x00003C00u, 0u);
}

// ---------------- K2: node pass 1 — h1 = tanh(...), z = h1@W2^T; seed aggs ----------------
__global__ void node1_kernel(const float4* __restrict__ x,
                             const float* __restrict__ W1,
                             const float* __restrict__ b1,
                             const float* __restrict__ W2) {
    __shared__ float sW1[26 * 4];
    __shared__ float sb1[26];
    __shared__ float sW2[11 * 26];
    int t = threadIdx.x;
    for (int i = t; i < 26 * 4; i += blockDim.x)  sW1[i] = W1[i];
    for (int i = t; i < 26; i += blockDim.x)      sb1[i] = b1[i];
    for (int i = t; i < 11 * 26; i += blockDim.x) sW2[i] = W2[i];
    __syncthreads();

    int i = blockIdx.x * blockDim.x + t;
    if (i >= N_NODES) return;

    uint4 sv = g_xs[i];
    float2 s01 = unpackh2(sv.x), s23 = unpackh2(sv.y);
    float  deg = unpackh2(sv.z).x;
    float4 xi = __ldg(&x[i]);                 // self-loop: exact f32
    float t0 = s01.x + xi.x, t1 = s01.y + xi.y;
    float t2 = s23.x + xi.z, t3 = s23.y + xi.w;
    float c1 = deg + 1.0f;

    float h[26];
#pragma unroll
    for (int j = 0; j < 26; j++) {
        float a = fmaf(sW1[j * 4 + 0], t0,
                  fmaf(sW1[j * 4 + 1], t1,
                  fmaf(sW1[j * 4 + 2], t2,
                  fmaf(sW1[j * 4 + 3], t3, c1 * sb1[j]))));
        h[j] = tanhf(a);
    }

    float z[11];
#pragma unroll
    for (int k = 0; k < 11; k++) {
        float a = 0.f;
#pragma unroll
        for (int j = 0; j < 26; j++) a = fmaf(sW2[k * 26 + j], h[j], a);
        z[k] = a;
    }

    // f16 record for the edge-2 gather (all channels feed the f16 reds raw)
    uint4 A;
    A.x = packh2(z[0], z[1]);  A.y = packh2(z[2], z[3]);
    A.z = packh2(z[4], z[5]);  A.w = packh2(z[6], z[7]);
    uint2 B = make_uint2(packh2(z[8], z[9]), packh2(z[10], 0.f));
    g_zh[i * 2]     = A;
    g_zh[i * 2 + 1] = make_uint4(B.x, B.y, 0u, 0u);

    // seed aggs with self-loop z
    g_aggA[i] = A;
    g_aggB[i] = B;
}

// ---------------- K3: edge pass 2 — TWO reds to SEPARATE arrays (distinct L2 lines) ----------------
__global__ void edge2_kernel(const int* __restrict__ ei) {
    int e = blockIdx.x * blockDim.x + threadIdx.x;
    if (e >= N_EDGES) return;
    int r = __ldg(&ei[e]);
    int c = __ldg(&ei[N_EDGES + e]);

    const uint4* zp = &g_zh[r * 2];
    uint4 A = __ldg(zp);                            // ch0..7, raw f16 words
    uint2 B = __ldg((const uint2*)(zp + 1));        // ch8..10 (+pad), same 32B sector

    redh8(&g_aggA[c], A.x, A.y, A.z, A.w);
    redh4(&g_aggB[c], B.x, B.y);
}

// ---------------- K4: node pass 2 — tanh, maxpool, graph-sum scatter ----------------
__global__ void node2_kernel(const float* __restrict__ b2) {
    __shared__ float sb2[11];
    int t = threadIdx.x;
    if (t < 11) sb2[t] = b2[t];
    __syncthreads();

    int i = blockIdx.x * blockDim.x + t;
    if (i >= N_NODES) return;

    float deg = unpackh2(g_xs[i].z).x;
    float c1 = deg + 1.0f;

    uint4 A = g_aggA[i];
    uint2 B = g_aggB[i];
    float2 a01 = unpackh2(A.x), a23 = unpackh2(A.y);
    float2 a45 = unpackh2(A.z), a67 = unpackh2(A.w);
    float2 a89 = unpackh2(B.x), aA_ = unpackh2(B.y);

    float av[11] = {a01.x, a01.y, a23.x, a23.y, a45.x, a45.y, a67.x, a67.y,
                    a89.x, a89.y, aA_.x};
    float v[11];
#pragma unroll
    for (int k = 0; k < 11; k++)
        v[k] = tanhf(av[k] + c1 * sb2[k]);

    // MaxPool1d(3, stride 3, left-pad 1): (-inf,v0,v1),(v2,v3,v4),(v5,v6,v7),(v8,v9,v10)
    float p0 = fmaxf(v[0], v[1]);
    float p1 = fmaxf(fmaxf(v[2], v[3]), v[4]);
    float p2 = fmaxf(fmaxf(v[5], v[6]), v[7]);
    float p3 = fmaxf(fmaxf(v[8], v[9]), v[10]);

    red4f((float*)&g_g4[i / GN], p0, p1, p2, p3);
}

// ---------------- K5: per-graph linear + softmax ----------------
__global__ void final_kernel(const float* __restrict__ Wl,
                             const float* __restrict__ bl,
                             float* __restrict__ out) {
    int g = blockIdx.x * blockDim.x + threadIdx.x;
    if (g >= N_GRAPHS) return;
    float4 gv = g_g4[g];
    float o0 = fmaf(Wl[0], gv.x, fmaf(Wl[1], gv.y, fmaf(Wl[2], gv.z, fmaf(Wl[3], gv.w, bl[0]))));
    float o1 = fmaf(Wl[4], gv.x, fmaf(Wl[5], gv.y, fmaf(Wl[6], gv.z, fmaf(Wl[7], gv.w, bl[1]))));
    float m = fmaxf(o0, o1);
    float e0 = expf(o0 - m), e1 = expf(o1 - m);
    float inv = 1.0f / (e0 + e1);
    out[g * 2 + 0] = e0 * inv;
    out[g * 2 + 1] = e1 * inv;
}

extern "C" void kernel_launch(void* const* d_in, const int* in_sizes, int n_in,
                              void* d_out, int out_size) {
    const float4* x  = (const float4*)d_in[0];   // [260000,4] f32
    const int*    ei = (const int*)d_in[1];      // [2, 8320000] i32
    const float*  W1 = (const float*)d_in[2];    // [26,4]
    const float*  b1 = (const float*)d_in[3];    // [26]
    const float*  W2 = (const float*)d_in[4];    // [11,26]
    const float*  b2 = (const float*)d_in[5];    // [11]
    const float*  Wl = (const float*)d_in[6];    // [2,4]
    const float*  bl = (const float*)d_in[7];    // [2]
    float* out = (float*)d_out;                  // [10000,2]

    const int T = 256;
    const int EB = (N_EDGES + T - 1) / T;
    const int NB = (N_NODES + T - 1) / T;

    init_kernel<<<NB, T>>>(x);
    edge1_kernel<<<EB, T>>>(ei);
    node1_kernel<<<NB, T>>>(x, W1, b1, W2);
    edge2_kernel<<<EB, T>>>(ei);
    node2_kernel<<<NB, T>>>(b2);
    final_kernel<<<(N_GRAPHS + T - 1) / T, T>>>(Wl, bl, out);
}